// round 2
// baseline (speedup 1.0000x reference)
#include <cuda_runtime.h>
#include <math.h>

// Problem constants
#define NSEQ   1024
#define DMODEL 640
#define NHEAD  8
#define DHEAD  80
#define NBATCH 2

// Scratch (allocation-free: __device__ globals)
__device__ float g_q[NBATCH * NSEQ * DMODEL];   // [2048,640]
__device__ float g_k[NBATCH * NSEQ * DMODEL];
__device__ float g_v[NBATCH * NSEQ * DMODEL];
__device__ float g_o[2 * NBATCH * NSEQ * DMODEL]; // [4096,640] merged-head attn output

// ---------------------------------------------------------------------------
// Generic fp32 SGEMM: C[M,N] = A[M,K] @ B[K,N] (+ bias[N] if bias != null)
// 128x128 tile, BK=8, 256 threads, 8x8 micro-tile per thread.
// Requires M%128==0, N%128==0, K%8==0 (true for all shapes here).
// ---------------------------------------------------------------------------
__global__ __launch_bounds__(256, 2)
void sgemm128(const float* __restrict__ A, const float* __restrict__ B,
              const float* __restrict__ bias, float* __restrict__ C,
              int M, int K, int N)
{
    __shared__ float As[8 * 128];   // transposed A tile: As[k][m]
    __shared__ float Bs[8 * 128];   // Bs[k][n]

    const int tid  = threadIdx.x;
    const int row0 = blockIdx.y * 128;
    const int col0 = blockIdx.x * 128;
    const int tx = tid & 15;        // 16 col-groups
    const int ty = tid >> 4;        // 16 row-groups

    // A tile loader: 128 rows x 8 cols, each thread one float4
    const int ar = tid >> 1;
    const int ac = (tid & 1) * 4;
    // B tile loader: 8 rows x 128 cols, each thread one float4
    const int br = tid >> 5;
    const int bc = (tid & 31) * 4;

    const float* Ap = A + (size_t)(row0 + ar) * K + ac;
    const float* Bp = B + (size_t)br * N + col0 + bc;

    float acc[8][8];
    #pragma unroll
    for (int i = 0; i < 8; i++)
        #pragma unroll
        for (int j = 0; j < 8; j++) acc[i][j] = 0.f;

    for (int k0 = 0; k0 < K; k0 += 8) {
        float4 av = *(const float4*)(Ap + k0);
        float4 bv = *(const float4*)(Bp + (size_t)k0 * N);
        __syncthreads();  // previous compute done before overwrite
        As[(ac + 0) * 128 + ar] = av.x;
        As[(ac + 1) * 128 + ar] = av.y;
        As[(ac + 2) * 128 + ar] = av.z;
        As[(ac + 3) * 128 + ar] = av.w;
        *(float4*)(Bs + br * 128 + bc) = bv;
        __syncthreads();

        #pragma unroll
        for (int kk = 0; kk < 8; kk++) {
            float4 a0 = *(const float4*)(As + kk * 128 + ty * 8);
            float4 a1 = *(const float4*)(As + kk * 128 + ty * 8 + 4);
            float4 b0 = *(const float4*)(Bs + kk * 128 + tx * 8);
            float4 b1 = *(const float4*)(Bs + kk * 128 + tx * 8 + 4);
            float a[8] = {a0.x, a0.y, a0.z, a0.w, a1.x, a1.y, a1.z, a1.w};
            float b[8] = {b0.x, b0.y, b0.z, b0.w, b1.x, b1.y, b1.z, b1.w};
            #pragma unroll
            for (int i = 0; i < 8; i++)
                #pragma unroll
                for (int j = 0; j < 8; j++)
                    acc[i][j] = fmaf(a[i], b[j], acc[i][j]);
        }
    }

    #pragma unroll
    for (int i = 0; i < 8; i++) {
        float* Cp = C + (size_t)(row0 + ty * 8 + i) * N + col0 + tx * 8;
        if (bias) {
            const float* bp = bias + col0 + tx * 8;
            #pragma unroll
            for (int j = 0; j < 8; j++) Cp[j] = acc[i][j] + bp[j];
        } else {
            #pragma unroll
            for (int j = 0; j < 8; j++) Cp[j] = acc[i][j];
        }
    }
}

// ---------------------------------------------------------------------------
// Flash-style masked attention.
// grid: x = 16 query blocks (64 q-rows each), y = 16 (b*8+h), z = 2 (0=fg,1=bg)
// 256 threads. Q tile in smem; per key-block of 64: S in registers (4x4/thread),
// online softmax (stats shared across 16-lane row groups via shfl), P staged
// through smem, PV accumulated in registers (4 rows x 5 cols / thread).
// Output written directly to merged-head layout g_o[(s*2+b)*1024+n][h*80+c].
// ---------------------------------------------------------------------------
#define QS_OFF   0
#define KS_OFF   (64 * 80)
#define VS_OFF   (KS_OFF + 64 * 81)
#define PS_OFF   (VS_OFF + 64 * 80)
#define ATTN_SMEM_FLOATS (PS_OFF + 64 * 64)
#define ATTN_SMEM_BYTES  (ATTN_SMEM_FLOATS * 4)

__global__ __launch_bounds__(256, 2)
void attn_kernel(const float* __restrict__ q, const float* __restrict__ k,
                 const float* __restrict__ v, const float* __restrict__ mask,
                 float* __restrict__ o)
{
    extern __shared__ float sm[];
    float* Qs = sm + QS_OFF;   // [64][80]
    float* Ks = sm + KS_OFF;   // [64][81] padded
    float* Vs = sm + VS_OFF;   // [64][80]
    float* Ps = sm + PS_OFF;   // [64][64]

    const int tid  = threadIdx.x;
    const int qb   = blockIdx.x;
    const int bh   = blockIdx.y;       // b*8 + h
    const int sfg  = blockIdx.z;       // 0 = fg, 1 = bg
    const int b    = bh >> 3;
    const int h    = bh & 7;
    const int qbase = qb * 64;

    const float* qhead = q + (size_t)(b * NSEQ) * DMODEL + h * DHEAD;
    const float* khead = k + (size_t)(b * NSEQ) * DMODEL + h * DHEAD;
    const float* vhead = v + (size_t)(b * NSEQ) * DMODEL + h * DHEAD;
    const float* mbase = mask + (size_t)bh * NSEQ * NSEQ;

    // Load Q tile [64,80]
    for (int idx = tid; idx < 64 * 80; idx += 256) {
        int r = idx / 80, c = idx % 80;
        Qs[r * 80 + c] = qhead[(size_t)(qbase + r) * DMODEL + c];
    }

    const int tx = tid & 15;   // S cols tx*4..+3 ; O cols tx*5..+4
    const int ty = tid >> 4;   // rows ty*4..+3 (both layouts)

    float m_i[4], l_i[4], acc[4][5];
    #pragma unroll
    for (int i = 0; i < 4; i++) {
        m_i[i] = -1e30f; l_i[i] = 0.f;
        #pragma unroll
        for (int c = 0; c < 5; c++) acc[i][c] = 0.f;
    }

    const float scale = 0.11180339887498949f;  // 80^-0.5

    for (int kb = 0; kb < NSEQ; kb += 64) {
        __syncthreads();  // prior PV done reading Vs/Ps; Q load done (first iter)
        // Load K and V blocks
        for (int idx = tid; idx < 64 * 80; idx += 256) {
            int r = idx / 80, c = idx % 80;
            Ks[r * 81 + c] = khead[(size_t)(kb + r) * DMODEL + c];
            Vs[r * 80 + c] = vhead[(size_t)(kb + r) * DMODEL + c];
        }
        __syncthreads();

        // S = Q K^T  (4x4 micro in registers)
        float s[4][4];
        #pragma unroll
        for (int i = 0; i < 4; i++)
            #pragma unroll
            for (int j = 0; j < 4; j++) s[i][j] = 0.f;

        const float* Qr = Qs + (ty * 4) * 80;
        const float* Kr = Ks + (tx * 4) * 81;
        #pragma unroll 4
        for (int c = 0; c < 80; c++) {
            float a0 = Qr[c], a1 = Qr[80 + c], a2 = Qr[160 + c], a3 = Qr[240 + c];
            float b0 = Kr[c], b1 = Kr[81 + c], b2 = Kr[162 + c], b3 = Kr[243 + c];
            s[0][0] = fmaf(a0, b0, s[0][0]); s[0][1] = fmaf(a0, b1, s[0][1]);
            s[0][2] = fmaf(a0, b2, s[0][2]); s[0][3] = fmaf(a0, b3, s[0][3]);
            s[1][0] = fmaf(a1, b0, s[1][0]); s[1][1] = fmaf(a1, b1, s[1][1]);
            s[1][2] = fmaf(a1, b2, s[1][2]); s[1][3] = fmaf(a1, b3, s[1][3]);
            s[2][0] = fmaf(a2, b0, s[2][0]); s[2][1] = fmaf(a2, b1, s[2][1]);
            s[2][2] = fmaf(a2, b2, s[2][2]); s[2][3] = fmaf(a2, b3, s[2][3]);
            s[3][0] = fmaf(a3, b0, s[3][0]); s[3][1] = fmaf(a3, b1, s[3][1]);
            s[3][2] = fmaf(a3, b2, s[3][2]); s[3][3] = fmaf(a3, b3, s[3][3]);
        }

        // scale + mask (fg: mask? s+1 : -inf ; bg: mask? -inf : s)
        float f[4];
        #pragma unroll
        for (int i = 0; i < 4; i++) {
            const float* mr = mbase + (size_t)(qbase + ty * 4 + i) * NSEQ + kb + tx * 4;
            float4 mv = *(const float4*)mr;
            float mm[4] = {mv.x, mv.y, mv.z, mv.w};
            #pragma unroll
            for (int j = 0; j < 4; j++) {
                float val = s[i][j] * scale;
                if (sfg == 0) s[i][j] = (mm[j] > 0.5f) ? (val + 1.0f) : -1e30f;
                else          s[i][j] = (mm[j] > 0.5f) ? -1e30f : val;
            }
        }

        // online softmax stats across the 16-lane row group
        #pragma unroll
        for (int i = 0; i < 4; i++) {
            float mx = fmaxf(fmaxf(s[i][0], s[i][1]), fmaxf(s[i][2], s[i][3]));
            #pragma unroll
            for (int off = 8; off > 0; off >>= 1)
                mx = fmaxf(mx, __shfl_xor_sync(0xffffffffu, mx, off));
            float nm = fmaxf(m_i[i], mx);
            float sum = 0.f;
            #pragma unroll
            for (int j = 0; j < 4; j++) {
                s[i][j] = __expf(s[i][j] - nm);
                sum += s[i][j];
            }
            #pragma unroll
            for (int off = 8; off > 0; off >>= 1)
                sum += __shfl_xor_sync(0xffffffffu, sum, off);
            f[i] = __expf(m_i[i] - nm);
            l_i[i] = l_i[i] * f[i] + sum;
            m_i[i] = nm;
        }

        // stage P to smem
        #pragma unroll
        for (int i = 0; i < 4; i++)
            #pragma unroll
            for (int j = 0; j < 4; j++)
                Ps[(ty * 4 + i) * 64 + tx * 4 + j] = s[i][j];
        __syncthreads();

        // O = O*f + P @ V   (rows ty*4+i, cols tx*5..+4)
        #pragma unroll
        for (int i = 0; i < 4; i++)
            #pragma unroll
            for (int c = 0; c < 5; c++) acc[i][c] *= f[i];

        const float* Pr = Ps + (ty * 4) * 64;
        const float* Vc = Vs + tx * 5;
        #pragma unroll 4
        for (int j = 0; j < 64; j++) {
            float p0 = Pr[j], p1 = Pr[64 + j], p2 = Pr[128 + j], p3 = Pr[192 + j];
            const float* vr = Vc + j * 80;
            #pragma unroll
            for (int c = 0; c < 5; c++) {
                float vv = vr[c];
                acc[0][c] = fmaf(p0, vv, acc[0][c]);
                acc[1][c] = fmaf(p1, vv, acc[1][c]);
                acc[2][c] = fmaf(p2, vv, acc[2][c]);
                acc[3][c] = fmaf(p3, vv, acc[3][c]);
            }
        }
    }

    // write merged-head output: batch index = sfg*2 + b
    const int obat = sfg * 2 + b;
    #pragma unroll
    for (int i = 0; i < 4; i++) {
        float inv = 1.0f / l_i[i];
        size_t row = (size_t)(obat * NSEQ + qbase + ty * 4 + i);
        float* op = o + row * DMODEL + h * DHEAD + tx * 5;
        #pragma unroll
        for (int c = 0; c < 5; c++) op[c] = acc[i][c] * inv;
    }
}

// ---------------------------------------------------------------------------
extern "C" void kernel_launch(void* const* d_in, const int* in_sizes, int n_in,
                              void* d_out, int out_size)
{
    const float* x   = (const float*)d_in[0];
    const float* msk = (const float*)d_in[1];
    const float* Wq  = (const float*)d_in[2];
    const float* Wk  = (const float*)d_in[3];
    const float* Wv  = (const float*)d_in[4];
    const float* Wo  = (const float*)d_in[5];
    const float* bo  = (const float*)d_in[6];
    float* out = (float*)d_out;

    float *q, *k, *v, *o;
    cudaGetSymbolAddress((void**)&q, g_q);
    cudaGetSymbolAddress((void**)&k, g_k);
    cudaGetSymbolAddress((void**)&v, g_v);
    cudaGetSymbolAddress((void**)&o, g_o);

    cudaFuncSetAttribute(attn_kernel,
                         cudaFuncAttributeMaxDynamicSharedMemorySize,
                         ATTN_SMEM_BYTES);

    // QKV projections: [2048,640] = x @ W
    dim3 gq(DMODEL / 128, (NBATCH * NSEQ) / 128);
    sgemm128<<<gq, 256>>>(x, Wq, nullptr, q, NBATCH * NSEQ, DMODEL, DMODEL);
    sgemm128<<<gq, 256>>>(x, Wk, nullptr, k, NBATCH * NSEQ, DMODEL, DMODEL);
    sgemm128<<<gq, 256>>>(x, Wv, nullptr, v, NBATCH * NSEQ, DMODEL, DMODEL);

    // Masked flash attention (fg + bg), writes merged-head g_o [4096,640]
    dim3 ga(NSEQ / 64, NBATCH * NHEAD, 2);
    attn_kernel<<<ga, 256, ATTN_SMEM_BYTES>>>(q, k, v, msk, o);

    // Output projection with bias: [4096,640] = g_o @ Wo + bo
    dim3 go(DMODEL / 128, (2 * NBATCH * NSEQ) / 128);
    sgemm128<<<go, 256>>>(o, Wo, bo, out, 2 * NBATCH * NSEQ, DMODEL, DMODEL);
}

// round 3
// speedup vs baseline: 3.8943x; 3.8943x over previous
#include <cuda_runtime.h>
#include <cuda_fp16.h>
#include <math.h>
#include <stdint.h>

#define NSEQ   1024
#define DMODEL 640
#define NHEAD  8
#define DHEAD  80
#define NBATCH 2
#define MROWS  (NBATCH * NSEQ)     // 2048
#define OROWS  (2 * NBATCH * NSEQ) // 4096

// ---------------- scratch (allocation-free) ----------------
__device__ __half g_xh [MROWS * DMODEL];
__device__ __half g_wqh[DMODEL * DMODEL];
__device__ __half g_wkh[DMODEL * DMODEL];
__device__ __half g_wvh[DMODEL * DMODEL];
__device__ __half g_woh[DMODEL * DMODEL];
__device__ __half g_qh [MROWS * DMODEL];
__device__ __half g_kh [MROWS * DMODEL];
__device__ __half g_vh [MROWS * DMODEL];
__device__ __half g_oh [OROWS * DMODEL];

// ---------------- helpers ----------------
__device__ __forceinline__ uint32_t sptr(const void* p) {
    return (uint32_t)__cvta_generic_to_shared(p);
}
__device__ __forceinline__ void ldsm4(uint32_t a, uint32_t& r0, uint32_t& r1,
                                      uint32_t& r2, uint32_t& r3) {
    asm volatile("ldmatrix.sync.aligned.m8n8.x4.shared.b16 {%0,%1,%2,%3},[%4];"
                 : "=r"(r0), "=r"(r1), "=r"(r2), "=r"(r3) : "r"(a));
}
__device__ __forceinline__ void ldsm4t(uint32_t a, uint32_t& r0, uint32_t& r1,
                                       uint32_t& r2, uint32_t& r3) {
    asm volatile("ldmatrix.sync.aligned.m8n8.x4.trans.shared.b16 {%0,%1,%2,%3},[%4];"
                 : "=r"(r0), "=r"(r1), "=r"(r2), "=r"(r3) : "r"(a));
}
__device__ __forceinline__ void mma16816(float* c, uint32_t a0, uint32_t a1,
                                         uint32_t a2, uint32_t a3,
                                         uint32_t b0, uint32_t b1) {
    asm volatile(
        "mma.sync.aligned.m16n8k16.row.col.f32.f16.f16.f32 "
        "{%0,%1,%2,%3},{%4,%5,%6,%7},{%8,%9},{%0,%1,%2,%3};"
        : "+f"(c[0]), "+f"(c[1]), "+f"(c[2]), "+f"(c[3])
        : "r"(a0), "r"(a1), "r"(a2), "r"(a3), "r"(b0), "r"(b1));
}
__device__ __forceinline__ uint32_t packh2(float lo, float hi) {
    __half2 h = __floats2half2_rn(lo, hi);
    return *reinterpret_cast<uint32_t*>(&h);
}

// ---------------- fp32 -> fp16 conversion (5 segments in one launch) ------
__global__ void conv_f2h(const float* __restrict__ x,  const float* __restrict__ wq,
                         const float* __restrict__ wk, const float* __restrict__ wv,
                         const float* __restrict__ wo) {
    int seg = blockIdx.y;
    const float* src; __half* dst; int n8;
    if      (seg == 0) { src = x;  dst = g_xh;  n8 = MROWS * DMODEL / 8; }
    else if (seg == 1) { src = wq; dst = g_wqh; n8 = DMODEL * DMODEL / 8; }
    else if (seg == 2) { src = wk; dst = g_wkh; n8 = DMODEL * DMODEL / 8; }
    else if (seg == 3) { src = wv; dst = g_wvh; n8 = DMODEL * DMODEL / 8; }
    else               { src = wo; dst = g_woh; n8 = DMODEL * DMODEL / 8; }
    for (int i = blockIdx.x * blockDim.x + threadIdx.x; i < n8;
         i += gridDim.x * blockDim.x) {
        float4 f0 = ((const float4*)src)[2 * i];
        float4 f1 = ((const float4*)src)[2 * i + 1];
        int4 o;
        o.x = packh2(f0.x, f0.y);
        o.y = packh2(f0.z, f0.w);
        o.z = packh2(f1.x, f1.y);
        o.w = packh2(f1.z, f1.w);
        ((int4*)dst)[i] = o;
    }
}

// ---------------- tensor-core HGEMM core ----------------
// C[M,N] = A[M,K] @ B[K,N], A/B fp16 row-major, fp32 accum.
// BM=128 BN=64 BK=32, 256 threads, warp grid 4(m) x 2(n), warp tile 32x32.
#define BM 128
#define BN 64
#define BK 32
#define LDA 40   // halfs, padded
#define LDB 72

template <bool HALF_OUT>
__device__ __forceinline__ void gemm_tile(const __half* __restrict__ A,
                                          const __half* __restrict__ B,
                                          const float* __restrict__ bias,
                                          float* Cf, __half* Ch,
                                          int M, int K, int N,
                                          int row0, int col0,
                                          __half* As, __half* Bs) {
    const int tid  = threadIdx.x;
    const int wid  = tid >> 5;
    const int lane = tid & 31;
    const int wm   = (wid & 3) * 32;   // warp rows
    const int wn   = (wid >> 2) * 32;  // warp cols

    // gmem tile loaders
    const int ar0 = tid >> 2, ac = (tid & 3) * 8;   // A: 2 int4/thread
    const int br  = tid >> 3, bc = (tid & 7) * 8;   // B: 1 int4/thread
    const int NIT = K / BK;

    float acc[2][4][4];
    #pragma unroll
    for (int i = 0; i < 2; i++)
        #pragma unroll
        for (int j = 0; j < 4; j++)
            #pragma unroll
            for (int t = 0; t < 4; t++) acc[i][j][t] = 0.f;

    // ldmatrix base addresses
    uint32_t a_base = sptr(As) +
        (((wm + (lane & 15)) * LDA + (lane >> 4) * 8) * 2);
    uint32_t b_base = sptr(Bs) +
        (((lane & 15) * LDB + wn + (lane >> 4) * 8) * 2);

    // preload tile 0
    int4 aR0 = *(const int4*)(A + (size_t)(row0 + ar0) * K + ac);
    int4 aR1 = *(const int4*)(A + (size_t)(row0 + ar0 + 64) * K + ac);
    int4 bR  = *(const int4*)(B + (size_t)br * N + col0 + bc);
    *(int4*)(As + ar0 * LDA + ac)        = aR0;
    *(int4*)(As + (ar0 + 64) * LDA + ac) = aR1;
    *(int4*)(Bs + br * LDB + bc)         = bR;
    __syncthreads();

    for (int it = 0; it < NIT; ++it) {
        if (it + 1 < NIT) {
            int k0n = (it + 1) * BK;
            aR0 = *(const int4*)(A + (size_t)(row0 + ar0) * K + k0n + ac);
            aR1 = *(const int4*)(A + (size_t)(row0 + ar0 + 64) * K + k0n + ac);
            bR  = *(const int4*)(B + (size_t)(k0n + br) * N + col0 + bc);
        }
        #pragma unroll
        for (int kc = 0; kc < 2; ++kc) {
            uint32_t af[2][4];
            #pragma unroll
            for (int i = 0; i < 2; i++)
                ldsm4(a_base + (i * 16 * LDA + kc * 16) * 2,
                      af[i][0], af[i][1], af[i][2], af[i][3]);
            uint32_t bf[4][2];
            #pragma unroll
            for (int j2 = 0; j2 < 2; j2++) {
                uint32_t r0, r1, r2, r3;
                ldsm4t(b_base + (kc * 16 * LDB + j2 * 16) * 2, r0, r1, r2, r3);
                bf[j2 * 2][0] = r0; bf[j2 * 2][1] = r1;
                bf[j2 * 2 + 1][0] = r2; bf[j2 * 2 + 1][1] = r3;
            }
            #pragma unroll
            for (int i = 0; i < 2; i++)
                #pragma unroll
                for (int j = 0; j < 4; j++)
                    mma16816(acc[i][j], af[i][0], af[i][1], af[i][2], af[i][3],
                             bf[j][0], bf[j][1]);
        }
        __syncthreads();
        if (it + 1 < NIT) {
            *(int4*)(As + ar0 * LDA + ac)        = aR0;
            *(int4*)(As + (ar0 + 64) * LDA + ac) = aR1;
            *(int4*)(Bs + br * LDB + bc)         = bR;
            __syncthreads();
        }
    }

    // epilogue
    #pragma unroll
    for (int i = 0; i < 2; i++) {
        int r_lo = row0 + wm + i * 16 + (lane >> 2);
        #pragma unroll
        for (int j = 0; j < 4; j++) {
            int c = col0 + wn + j * 8 + (lane & 3) * 2;
            if (HALF_OUT) {
                *(half2*)(Ch + (size_t)r_lo * N + c) =
                    __floats2half2_rn(acc[i][j][0], acc[i][j][1]);
                *(half2*)(Ch + (size_t)(r_lo + 8) * N + c) =
                    __floats2half2_rn(acc[i][j][2], acc[i][j][3]);
            } else {
                float b0 = bias[c], b1 = bias[c + 1];
                *(float2*)(Cf + (size_t)r_lo * N + c) =
                    make_float2(acc[i][j][0] + b0, acc[i][j][1] + b1);
                *(float2*)(Cf + (size_t)(r_lo + 8) * N + c) =
                    make_float2(acc[i][j][2] + b0, acc[i][j][3] + b1);
            }
        }
    }
}

// QKV projections fused: z selects (Wq,q) / (Wk,k) / (Wv,v)
__global__ __launch_bounds__(256) void qkv_gemm() {
    __shared__ __half As[BM * LDA];
    __shared__ __half Bs[BK * LDB];
    int z = blockIdx.z;
    const __half* W = (z == 0) ? g_wqh : (z == 1) ? g_wkh : g_wvh;
    __half*       O = (z == 0) ? g_qh  : (z == 1) ? g_kh  : g_vh;
    gemm_tile<true>(g_xh, W, nullptr, nullptr, O, MROWS, DMODEL, DMODEL,
                    blockIdx.y * BM, blockIdx.x * BN, As, Bs);
}

// Output projection: fp32 out + bias
__global__ __launch_bounds__(256) void out_gemm(const float* __restrict__ bias,
                                                float* __restrict__ out) {
    __shared__ __half As[BM * LDA];
    __shared__ __half Bs[BK * LDB];
    gemm_tile<false>(g_oh, g_woh, bias, out, nullptr, OROWS, DMODEL, DMODEL,
                     blockIdx.y * BM, blockIdx.x * BN, As, Bs);
}

// ---------------- FA2-style fp16 masked attention ----------------
// grid (16 q-blocks, 16 bh, 2 fg/bg); 128 threads (4 warps, 16 q-rows each).
#define ALD 88  // padded row stride (halfs) for 80-wide tiles

__global__ __launch_bounds__(128) void attn_f16(const float* __restrict__ mask) {
    __shared__ __half Qs[64 * ALD];
    __shared__ __half Ks[64 * ALD];
    __shared__ __half Vs[64 * ALD];

    const int tid  = threadIdx.x;
    const int wid  = tid >> 5;
    const int lane = tid & 31;
    const int qb = blockIdx.x, bh = blockIdx.y, z = blockIdx.z;
    const int b = bh >> 3, h = bh & 7;
    const int qbase = qb * 64;

    const __half* qh = g_qh + (size_t)b * NSEQ * DMODEL + h * DHEAD;
    const __half* kh = g_kh + (size_t)b * NSEQ * DMODEL + h * DHEAD;
    const __half* vh = g_vh + (size_t)b * NSEQ * DMODEL + h * DHEAD;
    const float* mbase = mask + (size_t)bh * NSEQ * NSEQ;

    // load Q tile [64][80]
    for (int i = tid; i < 64 * 10; i += 128) {
        int r = i / 10, c = (i % 10) * 8;
        *(int4*)(Qs + r * ALD + c) =
            *(const int4*)(qh + (size_t)(qbase + r) * DMODEL + c);
    }
    __syncthreads();

    // Q fragments (5 k-chunks of 16)
    uint32_t qf[5][4];
    {
        uint32_t base = sptr(Qs) +
            (((wid * 16 + (lane & 15)) * ALD + (lane >> 4) * 8) * 2);
        #pragma unroll
        for (int kc = 0; kc < 5; kc++)
            ldsm4(base + kc * 16 * 2, qf[kc][0], qf[kc][1], qf[kc][2], qf[kc][3]);
    }

    float oacc[10][4];
    #pragma unroll
    for (int d = 0; d < 10; d++)
        #pragma unroll
        for (int t = 0; t < 4; t++) oacc[d][t] = 0.f;
    float m0 = -1e30f, m1 = -1e30f, l0 = 0.f, l1 = 0.f;

    // ldmatrix bases
    const uint32_t kfb = sptr(Ks) +
        ((((lane & 7) + ((lane & 16) >> 1)) * ALD + (lane & 8)) * 2);
    const uint32_t vfb = sptr(Vs) +
        (((lane & 15) * ALD + (lane >> 4) * 8) * 2);

    const float scale = 0.11180339887498949f;  // 80^-0.5
    const int rowg = qbase + wid * 16 + (lane >> 2);

    for (int kb = 0; kb < NSEQ; kb += 64) {
        __syncthreads();
        for (int i = tid; i < 64 * 10; i += 128) {
            int r = i / 10, c = (i % 10) * 8;
            *(int4*)(Ks + r * ALD + c) =
                *(const int4*)(kh + (size_t)(kb + r) * DMODEL + c);
            *(int4*)(Vs + r * ALD + c) =
                *(const int4*)(vh + (size_t)(kb + r) * DMODEL + c);
        }
        __syncthreads();

        // S = Q K^T : 8 n-tiles (keys) in C-frags
        float s[8][4];
        #pragma unroll
        for (int j = 0; j < 8; j++)
            #pragma unroll
            for (int t = 0; t < 4; t++) s[j][t] = 0.f;
        #pragma unroll
        for (int kc = 0; kc < 5; kc++) {
            #pragma unroll
            for (int j2 = 0; j2 < 4; j2++) {
                uint32_t r0, r1, r2, r3;
                ldsm4(kfb + (j2 * 16 * ALD + kc * 16) * 2, r0, r1, r2, r3);
                mma16816(s[j2 * 2],     qf[kc][0], qf[kc][1], qf[kc][2], qf[kc][3], r0, r1);
                mma16816(s[j2 * 2 + 1], qf[kc][0], qf[kc][1], qf[kc][2], qf[kc][3], r2, r3);
            }
        }

        // scale + mask
        #pragma unroll
        for (int j = 0; j < 8; j++) {
            int col = kb + j * 8 + (lane & 3) * 2;
            float2 ma = *(const float2*)(mbase + (size_t)rowg * NSEQ + col);
            float2 mb = *(const float2*)(mbase + (size_t)(rowg + 8) * NSEQ + col);
            if (z == 0) {
                s[j][0] = (ma.x > 0.5f) ? s[j][0] * scale + 1.f : -1e30f;
                s[j][1] = (ma.y > 0.5f) ? s[j][1] * scale + 1.f : -1e30f;
                s[j][2] = (mb.x > 0.5f) ? s[j][2] * scale + 1.f : -1e30f;
                s[j][3] = (mb.y > 0.5f) ? s[j][3] * scale + 1.f : -1e30f;
            } else {
                s[j][0] = (ma.x > 0.5f) ? -1e30f : s[j][0] * scale;
                s[j][1] = (ma.y > 0.5f) ? -1e30f : s[j][1] * scale;
                s[j][2] = (mb.x > 0.5f) ? -1e30f : s[j][2] * scale;
                s[j][3] = (mb.y > 0.5f) ? -1e30f : s[j][3] * scale;
            }
        }

        // online softmax (rows rowg and rowg+8, quad reduction)
        float mx0 = -1e30f, mx1 = -1e30f;
        #pragma unroll
        for (int j = 0; j < 8; j++) {
            mx0 = fmaxf(mx0, fmaxf(s[j][0], s[j][1]));
            mx1 = fmaxf(mx1, fmaxf(s[j][2], s[j][3]));
        }
        mx0 = fmaxf(mx0, __shfl_xor_sync(0xffffffffu, mx0, 1));
        mx0 = fmaxf(mx0, __shfl_xor_sync(0xffffffffu, mx0, 2));
        mx1 = fmaxf(mx1, __shfl_xor_sync(0xffffffffu, mx1, 1));
        mx1 = fmaxf(mx1, __shfl_xor_sync(0xffffffffu, mx1, 2));
        float nm0 = fmaxf(m0, mx0), nm1 = fmaxf(m1, mx1);
        float f0 = __expf(m0 - nm0), f1 = __expf(m1 - nm1);
        float sum0 = 0.f, sum1 = 0.f;
        #pragma unroll
        for (int j = 0; j < 8; j++) {
            s[j][0] = __expf(s[j][0] - nm0);
            s[j][1] = __expf(s[j][1] - nm0);
            s[j][2] = __expf(s[j][2] - nm1);
            s[j][3] = __expf(s[j][3] - nm1);
            sum0 += s[j][0] + s[j][1];
            sum1 += s[j][2] + s[j][3];
        }
        sum0 += __shfl_xor_sync(0xffffffffu, sum0, 1);
        sum0 += __shfl_xor_sync(0xffffffffu, sum0, 2);
        sum1 += __shfl_xor_sync(0xffffffffu, sum1, 1);
        sum1 += __shfl_xor_sync(0xffffffffu, sum1, 2);
        l0 = l0 * f0 + sum0;
        l1 = l1 * f1 + sum1;
        m0 = nm0; m1 = nm1;

        #pragma unroll
        for (int d = 0; d < 10; d++) {
            oacc[d][0] *= f0; oacc[d][1] *= f0;
            oacc[d][2] *= f1; oacc[d][3] *= f1;
        }

        // PV: repack P C-frags -> A-frags in registers (exact layout match)
        #pragma unroll
        for (int kc = 0; kc < 4; kc++) {
            uint32_t a0 = packh2(s[2 * kc][0],     s[2 * kc][1]);
            uint32_t a1 = packh2(s[2 * kc][2],     s[2 * kc][3]);
            uint32_t a2 = packh2(s[2 * kc + 1][0], s[2 * kc + 1][1]);
            uint32_t a3 = packh2(s[2 * kc + 1][2], s[2 * kc + 1][3]);
            #pragma unroll
            for (int j = 0; j < 5; j++) {
                uint32_t r0, r1, r2, r3;
                ldsm4t(vfb + (kc * 16 * ALD + j * 16) * 2, r0, r1, r2, r3);
                mma16816(oacc[2 * j],     a0, a1, a2, a3, r0, r1);
                mma16816(oacc[2 * j + 1], a0, a1, a2, a3, r2, r3);
            }
        }
    }

    // epilogue: normalize, store fp16 merged-head output
    float i0 = 1.f / l0, i1 = 1.f / l1;
    const int obat = z * 2 + b;
    const int grow = obat * NSEQ + qbase + wid * 16 + (lane >> 2);
    #pragma unroll
    for (int d = 0; d < 10; d++) {
        int c = h * DHEAD + d * 8 + (lane & 3) * 2;
        *(half2*)(g_oh + (size_t)grow * DMODEL + c) =
            __floats2half2_rn(oacc[d][0] * i0, oacc[d][1] * i0);
        *(half2*)(g_oh + (size_t)(grow + 8) * DMODEL + c) =
            __floats2half2_rn(oacc[d][2] * i1, oacc[d][3] * i1);
    }
}

// ---------------------------------------------------------------------------
extern "C" void kernel_launch(void* const* d_in, const int* in_sizes, int n_in,
                              void* d_out, int out_size) {
    const float* x   = (const float*)d_in[0];
    const float* msk = (const float*)d_in[1];
    const float* Wq  = (const float*)d_in[2];
    const float* Wk  = (const float*)d_in[3];
    const float* Wv  = (const float*)d_in[4];
    const float* Wo  = (const float*)d_in[5];
    const float* bo  = (const float*)d_in[6];
    float* out = (float*)d_out;

    // 1) fp32 -> fp16 conversions
    conv_f2h<<<dim3(160, 5), 256>>>(x, Wq, Wk, Wv, Wo);

    // 2) QKV projections (fused, tensor cores)
    qkv_gemm<<<dim3(DMODEL / BN, MROWS / BM, 3), 256>>>();

    // 3) masked flash attention (fg + bg)
    attn_f16<<<dim3(NSEQ / 64, NBATCH * NHEAD, 2), 128>>>(msk);

    // 4) output projection + bias
    out_gemm<<<dim3(DMODEL / BN, OROWS / BM), 256>>>(bo, out);
}

// round 4
// speedup vs baseline: 7.8683x; 2.0205x over previous
#include <cuda_runtime.h>
#include <cuda_fp16.h>
#include <math.h>
#include <stdint.h>

#define NSEQ   1024
#define DMODEL 640
#define NHEAD  8
#define DHEAD  80
#define NBATCH 2
#define MROWS  (NBATCH * NSEQ)     // 2048
#define OROWS  (2 * NBATCH * NSEQ) // 4096

// ---------------- scratch (allocation-free) ----------------
__device__ __half g_xh [MROWS * DMODEL];
__device__ __half g_wqh[DMODEL * DMODEL];
__device__ __half g_wkh[DMODEL * DMODEL];
__device__ __half g_wvh[DMODEL * DMODEL];
__device__ __half g_woh[DMODEL * DMODEL];
__device__ __half g_qh [MROWS * DMODEL];
__device__ __half g_kh [MROWS * DMODEL];
__device__ __half g_vh [MROWS * DMODEL];
__device__ __half g_oh [OROWS * DMODEL];

// ---------------- helpers ----------------
__device__ __forceinline__ uint32_t sptr(const void* p) {
    return (uint32_t)__cvta_generic_to_shared(p);
}
__device__ __forceinline__ void ldsm4(uint32_t a, uint32_t& r0, uint32_t& r1,
                                      uint32_t& r2, uint32_t& r3) {
    asm volatile("ldmatrix.sync.aligned.m8n8.x4.shared.b16 {%0,%1,%2,%3},[%4];"
                 : "=r"(r0), "=r"(r1), "=r"(r2), "=r"(r3) : "r"(a));
}
__device__ __forceinline__ void ldsm4t(uint32_t a, uint32_t& r0, uint32_t& r1,
                                       uint32_t& r2, uint32_t& r3) {
    asm volatile("ldmatrix.sync.aligned.m8n8.x4.trans.shared.b16 {%0,%1,%2,%3},[%4];"
                 : "=r"(r0), "=r"(r1), "=r"(r2), "=r"(r3) : "r"(a));
}
__device__ __forceinline__ void mma16816(float* c, uint32_t a0, uint32_t a1,
                                         uint32_t a2, uint32_t a3,
                                         uint32_t b0, uint32_t b1) {
    asm volatile(
        "mma.sync.aligned.m16n8k16.row.col.f32.f16.f16.f32 "
        "{%0,%1,%2,%3},{%4,%5,%6,%7},{%8,%9},{%0,%1,%2,%3};"
        : "+f"(c[0]), "+f"(c[1]), "+f"(c[2]), "+f"(c[3])
        : "r"(a0), "r"(a1), "r"(a2), "r"(a3), "r"(b0), "r"(b1));
}
__device__ __forceinline__ uint32_t packh2(float lo, float hi) {
    __half2 h = __floats2half2_rn(lo, hi);
    return *reinterpret_cast<uint32_t*>(&h);
}
__device__ __forceinline__ void cpa16(uint32_t s, const void* g) {
    asm volatile("cp.async.cg.shared.global [%0], [%1], 16;" :: "r"(s), "l"(g));
}
__device__ __forceinline__ void cpa_commit() {
    asm volatile("cp.async.commit_group;");
}
__device__ __forceinline__ void cpa_wait0() {
    asm volatile("cp.async.wait_group 0;");
}
__device__ __forceinline__ void cpa_wait1() {
    asm volatile("cp.async.wait_group 1;");
}

// ---------------- fp32 -> fp16 conversion ----------------
__global__ void conv_f2h(const float* __restrict__ x,  const float* __restrict__ wq,
                         const float* __restrict__ wk, const float* __restrict__ wv,
                         const float* __restrict__ wo) {
    int seg = blockIdx.y;
    const float* src; __half* dst; int n8;
    if      (seg == 0) { src = x;  dst = g_xh;  n8 = MROWS * DMODEL / 8; }
    else if (seg == 1) { src = wq; dst = g_wqh; n8 = DMODEL * DMODEL / 8; }
    else if (seg == 2) { src = wk; dst = g_wkh; n8 = DMODEL * DMODEL / 8; }
    else if (seg == 3) { src = wv; dst = g_wvh; n8 = DMODEL * DMODEL / 8; }
    else               { src = wo; dst = g_woh; n8 = DMODEL * DMODEL / 8; }
    for (int i = blockIdx.x * blockDim.x + threadIdx.x; i < n8;
         i += gridDim.x * blockDim.x) {
        float4 f0 = ((const float4*)src)[2 * i];
        float4 f1 = ((const float4*)src)[2 * i + 1];
        int4 o;
        o.x = packh2(f0.x, f0.y);
        o.y = packh2(f0.z, f0.w);
        o.z = packh2(f1.x, f1.y);
        o.w = packh2(f1.z, f1.w);
        ((int4*)dst)[i] = o;
    }
}

// ---------------- tensor-core HGEMM, 2-stage cp.async pipeline -------------
// C[M,N] = A[M,K] @ B[K,N]; BM=128 BN=64 BK=32, 256 thr, warp grid 4x2.
#define BM 128
#define BN 64
#define BK 32
#define LDA 40   // halfs
#define LDB 72
#define ASTG (BM * LDA)   // halfs per A stage
#define BSTG (BK * LDB)

template <bool HALF_OUT>
__device__ __forceinline__ void gemm_tile(const __half* __restrict__ A,
                                          const __half* __restrict__ B,
                                          const float* __restrict__ bias,
                                          float* Cf, __half* Ch,
                                          int M, int K, int N,
                                          int row0, int col0,
                                          __half* As, __half* Bs) {
    const int tid  = threadIdx.x;
    const int wid  = tid >> 5;
    const int lane = tid & 31;
    const int wm   = (wid & 3) * 32;
    const int wn   = (wid >> 2) * 32;

    const int ar0 = tid >> 2, ac = (tid & 3) * 8;
    const int br  = tid >> 3, bc = (tid & 7) * 8;
    const int NIT = K / BK;

    const uint32_t sA = sptr(As);
    const uint32_t sB = sptr(Bs);
    const uint32_t a_st0 = sA + (ar0 * LDA + ac) * 2;
    const uint32_t a_st1 = sA + ((ar0 + 64) * LDA + ac) * 2;
    const uint32_t b_st  = sB + (br * LDB + bc) * 2;
    const __half* Ag0 = A + (size_t)(row0 + ar0) * K + ac;
    const __half* Ag1 = A + (size_t)(row0 + ar0 + 64) * K + ac;
    const __half* Bg  = B + (size_t)br * N + col0 + bc;

    float acc[2][4][4];
    #pragma unroll
    for (int i = 0; i < 2; i++)
        #pragma unroll
        for (int j = 0; j < 4; j++)
            #pragma unroll
            for (int t = 0; t < 4; t++) acc[i][j][t] = 0.f;

    const uint32_t a_base = sA + ((wm + (lane & 15)) * LDA + (lane >> 4) * 8) * 2;
    const uint32_t b_base = sB + ((lane & 15) * LDB + wn + (lane >> 4) * 8) * 2;

    // prefetch stage 0
    cpa16(a_st0, Ag0);
    cpa16(a_st1, Ag1);
    cpa16(b_st,  Bg);
    cpa_commit();

    for (int it = 0; it < NIT; ++it) {
        const int st = it & 1;
        if (it + 1 < NIT) {
            const int k0n = (it + 1) * BK;
            const int sn = (it + 1) & 1;
            cpa16(a_st0 + sn * ASTG * 2, Ag0 + k0n);
            cpa16(a_st1 + sn * ASTG * 2, Ag1 + k0n);
            cpa16(b_st  + sn * BSTG * 2, Bg + (size_t)k0n * N);
            cpa_commit();
            cpa_wait1();
        } else {
            cpa_wait0();
        }
        __syncthreads();

        const uint32_t ab = a_base + st * ASTG * 2;
        const uint32_t bb = b_base + st * BSTG * 2;
        #pragma unroll
        for (int kc = 0; kc < 2; ++kc) {
            uint32_t af[2][4];
            #pragma unroll
            for (int i = 0; i < 2; i++)
                ldsm4(ab + (i * 16 * LDA + kc * 16) * 2,
                      af[i][0], af[i][1], af[i][2], af[i][3]);
            uint32_t bf[4][2];
            #pragma unroll
            for (int j2 = 0; j2 < 2; j2++) {
                uint32_t r0, r1, r2, r3;
                ldsm4t(bb + (kc * 16 * LDB + j2 * 16) * 2, r0, r1, r2, r3);
                bf[j2 * 2][0] = r0; bf[j2 * 2][1] = r1;
                bf[j2 * 2 + 1][0] = r2; bf[j2 * 2 + 1][1] = r3;
            }
            #pragma unroll
            for (int i = 0; i < 2; i++)
                #pragma unroll
                for (int j = 0; j < 4; j++)
                    mma16816(acc[i][j], af[i][0], af[i][1], af[i][2], af[i][3],
                             bf[j][0], bf[j][1]);
        }
        __syncthreads();
    }

    #pragma unroll
    for (int i = 0; i < 2; i++) {
        int r_lo = row0 + wm + i * 16 + (lane >> 2);
        #pragma unroll
        for (int j = 0; j < 4; j++) {
            int c = col0 + wn + j * 8 + (lane & 3) * 2;
            if (HALF_OUT) {
                *(half2*)(Ch + (size_t)r_lo * N + c) =
                    __floats2half2_rn(acc[i][j][0], acc[i][j][1]);
                *(half2*)(Ch + (size_t)(r_lo + 8) * N + c) =
                    __floats2half2_rn(acc[i][j][2], acc[i][j][3]);
            } else {
                float b0 = bias[c], b1 = bias[c + 1];
                *(float2*)(Cf + (size_t)r_lo * N + c) =
                    make_float2(acc[i][j][0] + b0, acc[i][j][1] + b1);
                *(float2*)(Cf + (size_t)(r_lo + 8) * N + c) =
                    make_float2(acc[i][j][2] + b0, acc[i][j][3] + b1);
            }
        }
    }
}

__global__ __launch_bounds__(256) void qkv_gemm() {
    __shared__ __half As[2 * ASTG];
    __shared__ __half Bs[2 * BSTG];
    int z = blockIdx.z;
    const __half* W = (z == 0) ? g_wqh : (z == 1) ? g_wkh : g_wvh;
    __half*       O = (z == 0) ? g_qh  : (z == 1) ? g_kh  : g_vh;
    gemm_tile<true>(g_xh, W, nullptr, nullptr, O, MROWS, DMODEL, DMODEL,
                    blockIdx.y * BM, blockIdx.x * BN, As, Bs);
}

__global__ __launch_bounds__(256) void out_gemm(const float* __restrict__ bias,
                                                float* __restrict__ out) {
    __shared__ __half As[2 * ASTG];
    __shared__ __half Bs[2 * BSTG];
    gemm_tile<false>(g_oh, g_woh, bias, out, nullptr, OROWS, DMODEL, DMODEL,
                     blockIdx.y * BM, blockIdx.x * BN, As, Bs);
}

// ---------------- fused fg+bg fp16 masked flash attention ------------------
// grid (16 q-blocks, 16 bh); 128 threads (4 warps, 16 q-rows each).
// One CTA computes S once, runs BOTH mask streams (fg: z=0, bg: z=1).
#define ALD  88                  // padded row stride (halfs)
#define ATILE (64 * ALD)         // halfs per tile
#define ATT_SMEM ((1 + 4) * ATILE * 2)  // Q + 2x(K,V) stages, bytes

template <int Z>
__device__ __forceinline__ float mval(float sv, uint32_t bit) {
    if (Z == 0) return bit ? sv + 1.f : -1e30f;   // fg: keep mask==1, +1
    else        return bit ? -1e30f : sv;          // bg: keep mask==0
}

template <int Z>
__device__ __forceinline__ void softmax_stream(
    const float (&s)[8][4], uint32_t mbits,
    float& m0, float& m1, float& l0, float& l1,
    float& f0, float& f1, uint32_t (&pk)[4][4])
{
    float mx0 = -1e30f, mx1 = -1e30f;
    #pragma unroll
    for (int j = 0; j < 8; j++) {
        mx0 = fmaxf(mx0, fmaxf(mval<Z>(s[j][0], (mbits >> (j*4+0)) & 1),
                               mval<Z>(s[j][1], (mbits >> (j*4+1)) & 1)));
        mx1 = fmaxf(mx1, fmaxf(mval<Z>(s[j][2], (mbits >> (j*4+2)) & 1),
                               mval<Z>(s[j][3], (mbits >> (j*4+3)) & 1)));
    }
    mx0 = fmaxf(mx0, __shfl_xor_sync(0xffffffffu, mx0, 1));
    mx0 = fmaxf(mx0, __shfl_xor_sync(0xffffffffu, mx0, 2));
    mx1 = fmaxf(mx1, __shfl_xor_sync(0xffffffffu, mx1, 1));
    mx1 = fmaxf(mx1, __shfl_xor_sync(0xffffffffu, mx1, 2));
    const float nm0 = fmaxf(m0, mx0), nm1 = fmaxf(m1, mx1);
    f0 = __expf(m0 - nm0);
    f1 = __expf(m1 - nm1);
    float sum0 = 0.f, sum1 = 0.f;
    #pragma unroll
    for (int kc = 0; kc < 4; kc++) {
        const int j0 = 2 * kc, j1 = 2 * kc + 1;
        float e00 = __expf(mval<Z>(s[j0][0], (mbits >> (j0*4+0)) & 1) - nm0);
        float e01 = __expf(mval<Z>(s[j0][1], (mbits >> (j0*4+1)) & 1) - nm0);
        float e02 = __expf(mval<Z>(s[j0][2], (mbits >> (j0*4+2)) & 1) - nm1);
        float e03 = __expf(mval<Z>(s[j0][3], (mbits >> (j0*4+3)) & 1) - nm1);
        float e10 = __expf(mval<Z>(s[j1][0], (mbits >> (j1*4+0)) & 1) - nm0);
        float e11 = __expf(mval<Z>(s[j1][1], (mbits >> (j1*4+1)) & 1) - nm0);
        float e12 = __expf(mval<Z>(s[j1][2], (mbits >> (j1*4+2)) & 1) - nm1);
        float e13 = __expf(mval<Z>(s[j1][3], (mbits >> (j1*4+3)) & 1) - nm1);
        pk[kc][0] = packh2(e00, e01);
        pk[kc][1] = packh2(e02, e03);
        pk[kc][2] = packh2(e10, e11);
        pk[kc][3] = packh2(e12, e13);
        sum0 += (e00 + e01) + (e10 + e11);
        sum1 += (e02 + e03) + (e12 + e13);
    }
    sum0 += __shfl_xor_sync(0xffffffffu, sum0, 1);
    sum0 += __shfl_xor_sync(0xffffffffu, sum0, 2);
    sum1 += __shfl_xor_sync(0xffffffffu, sum1, 1);
    sum1 += __shfl_xor_sync(0xffffffffu, sum1, 2);
    l0 = l0 * f0 + sum0;
    l1 = l1 * f1 + sum1;
    m0 = nm0; m1 = nm1;
}

__global__ __launch_bounds__(128, 1) void attn_f16(const float* __restrict__ mask) {
    extern __shared__ __half sm[];
    __half* Qs = sm;                               // [64][ALD]

    const int tid  = threadIdx.x;
    const int wid  = tid >> 5;
    const int lane = tid & 31;
    const int qb = blockIdx.x, bh = blockIdx.y;
    const int b = bh >> 3, h = bh & 7;
    const int qbase = qb * 64;

    const __half* qh = g_qh + (size_t)b * NSEQ * DMODEL + h * DHEAD;
    const __half* kh = g_kh + (size_t)b * NSEQ * DMODEL + h * DHEAD;
    const __half* vh = g_vh + (size_t)b * NSEQ * DMODEL + h * DHEAD;
    const float* mbase = mask + (size_t)bh * NSEQ * NSEQ;

    // K/V double-buffer smem addresses
    const uint32_t smb = sptr(sm);
    // buffers: K0 at tile1, V0 tile2, K1 tile3, V1 tile4
    // prefetch KV block 0 (stage 0)
    {
        const uint32_t k0 = smb + (1 * ATILE) * 2;
        const uint32_t v0 = smb + (2 * ATILE) * 2;
        #pragma unroll
        for (int i = tid; i < 640; i += 128) {
            int r = i / 10, c = (i % 10) * 8;
            cpa16(k0 + (r * ALD + c) * 2, kh + (size_t)r * DMODEL + c);
            cpa16(v0 + (r * ALD + c) * 2, vh + (size_t)r * DMODEL + c);
        }
        cpa_commit();
    }

    // load Q tile [64][80]
    for (int i = tid; i < 640; i += 128) {
        int r = i / 10, c = (i % 10) * 8;
        *(int4*)(Qs + r * ALD + c) =
            *(const int4*)(qh + (size_t)(qbase + r) * DMODEL + c);
    }
    __syncthreads();

    // Q fragments (5 k-chunks)
    uint32_t qf[5][4];
    {
        uint32_t base = smb + ((wid * 16 + (lane & 15)) * ALD + (lane >> 4) * 8) * 2;
        #pragma unroll
        for (int kc = 0; kc < 5; kc++)
            ldsm4(base + kc * 16 * 2, qf[kc][0], qf[kc][1], qf[kc][2], qf[kc][3]);
    }

    float oA[10][4], oB[10][4];
    #pragma unroll
    for (int d = 0; d < 10; d++)
        #pragma unroll
        for (int t = 0; t < 4; t++) { oA[d][t] = 0.f; oB[d][t] = 0.f; }
    float mA0 = -1e30f, mA1 = -1e30f, lA0 = 0.f, lA1 = 0.f;
    float mB0 = -1e30f, mB1 = -1e30f, lB0 = 0.f, lB1 = 0.f;

    const uint32_t kf_off = (((lane & 7) + ((lane & 16) >> 1)) * ALD + (lane & 8)) * 2;
    const uint32_t vf_off = ((lane & 15) * ALD + (lane >> 4) * 8) * 2;
    const float scale = 0.11180339887498949f;  // 80^-0.5
    const int rowg = qbase + wid * 16 + (lane >> 2);

    for (int ib = 0; ib < 16; ib++) {
        const int kb = ib * 64;
        const int st = ib & 1;
        // prefetch next KV block into other stage
        if (ib + 1 < 16) {
            const int sn = (ib + 1) & 1;
            const uint32_t kn = smb + ((1 + 2 * sn) * ATILE) * 2;
            const uint32_t vn = smb + ((2 + 2 * sn) * ATILE) * 2;
            const __half* kg = kh + (size_t)(kb + 64) * DMODEL;
            const __half* vg = vh + (size_t)(kb + 64) * DMODEL;
            #pragma unroll
            for (int i = tid; i < 640; i += 128) {
                int r = i / 10, c = (i % 10) * 8;
                cpa16(kn + (r * ALD + c) * 2, kg + (size_t)r * DMODEL + c);
                cpa16(vn + (r * ALD + c) * 2, vg + (size_t)r * DMODEL + c);
            }
            cpa_commit();
            cpa_wait1();
        } else {
            cpa_wait0();
        }
        __syncthreads();

        const uint32_t kfb = smb + ((1 + 2 * st) * ATILE) * 2 + kf_off;
        const uint32_t vfb = smb + ((2 + 2 * st) * ATILE) * 2 + vf_off;

        // S = Q K^T (once for both streams)
        float s[8][4];
        #pragma unroll
        for (int j = 0; j < 8; j++)
            #pragma unroll
            for (int t = 0; t < 4; t++) s[j][t] = 0.f;
        #pragma unroll
        for (int kc = 0; kc < 5; kc++) {
            #pragma unroll
            for (int j2 = 0; j2 < 4; j2++) {
                uint32_t r0, r1, r2, r3;
                ldsm4(kfb + (j2 * 16 * ALD + kc * 16) * 2, r0, r1, r2, r3);
                mma16816(s[j2 * 2],     qf[kc][0], qf[kc][1], qf[kc][2], qf[kc][3], r0, r1);
                mma16816(s[j2 * 2 + 1], qf[kc][0], qf[kc][1], qf[kc][2], qf[kc][3], r2, r3);
            }
        }

        // scale + mask bitmask
        uint32_t mbits = 0;
        #pragma unroll
        for (int j = 0; j < 8; j++) {
            int col = kb + j * 8 + (lane & 3) * 2;
            float2 ma = *(const float2*)(mbase + (size_t)rowg * NSEQ + col);
            float2 mb = *(const float2*)(mbase + (size_t)(rowg + 8) * NSEQ + col);
            s[j][0] *= scale; s[j][1] *= scale;
            s[j][2] *= scale; s[j][3] *= scale;
            if (ma.x > 0.5f) mbits |= 1u << (j * 4 + 0);
            if (ma.y > 0.5f) mbits |= 1u << (j * 4 + 1);
            if (mb.x > 0.5f) mbits |= 1u << (j * 4 + 2);
            if (mb.y > 0.5f) mbits |= 1u << (j * 4 + 3);
        }

        // two softmax streams
        uint32_t pkA[4][4], pkB[4][4];
        float fA0, fA1, fB0, fB1;
        softmax_stream<0>(s, mbits, mA0, mA1, lA0, lA1, fA0, fA1, pkA);
        softmax_stream<1>(s, mbits, mB0, mB1, lB0, lB1, fB0, fB1, pkB);

        #pragma unroll
        for (int d = 0; d < 10; d++) {
            oA[d][0] *= fA0; oA[d][1] *= fA0; oA[d][2] *= fA1; oA[d][3] *= fA1;
            oB[d][0] *= fB0; oB[d][1] *= fB0; oB[d][2] *= fB1; oB[d][3] *= fB1;
        }

        // PV for both streams, sharing each V fragment load
        #pragma unroll
        for (int kc = 0; kc < 4; kc++) {
            #pragma unroll
            for (int j = 0; j < 5; j++) {
                uint32_t r0, r1, r2, r3;
                ldsm4t(vfb + (kc * 16 * ALD + j * 16) * 2, r0, r1, r2, r3);
                mma16816(oA[2 * j],     pkA[kc][0], pkA[kc][1], pkA[kc][2], pkA[kc][3], r0, r1);
                mma16816(oA[2 * j + 1], pkA[kc][0], pkA[kc][1], pkA[kc][2], pkA[kc][3], r2, r3);
                mma16816(oB[2 * j],     pkB[kc][0], pkB[kc][1], pkB[kc][2], pkB[kc][3], r0, r1);
                mma16816(oB[2 * j + 1], pkB[kc][0], pkB[kc][1], pkB[kc][2], pkB[kc][3], r2, r3);
            }
        }
        __syncthreads();
    }

    // epilogue: normalize + store both stream outputs (merged-head fp16)
    const float iA0 = 1.f / lA0, iA1 = 1.f / lA1;
    const float iB0 = 1.f / lB0, iB1 = 1.f / lB1;
    const int growA = (b) * NSEQ + qbase + wid * 16 + (lane >> 2);
    const int growB = (2 + b) * NSEQ + qbase + wid * 16 + (lane >> 2);
    #pragma unroll
    for (int d = 0; d < 10; d++) {
        int c = h * DHEAD + d * 8 + (lane & 3) * 2;
        *(half2*)(g_oh + (size_t)growA * DMODEL + c) =
            __floats2half2_rn(oA[d][0] * iA0, oA[d][1] * iA0);
        *(half2*)(g_oh + (size_t)(growA + 8) * DMODEL + c) =
            __floats2half2_rn(oA[d][2] * iA1, oA[d][3] * iA1);
        *(half2*)(g_oh + (size_t)growB * DMODEL + c) =
            __floats2half2_rn(oB[d][0] * iB0, oB[d][1] * iB0);
        *(half2*)(g_oh + (size_t)(growB + 8) * DMODEL + c) =
            __floats2half2_rn(oB[d][2] * iB1, oB[d][3] * iB1);
    }
}

// ---------------------------------------------------------------------------
extern "C" void kernel_launch(void* const* d_in, const int* in_sizes, int n_in,
                              void* d_out, int out_size) {
    const float* x   = (const float*)d_in[0];
    const float* msk = (const float*)d_in[1];
    const float* Wq  = (const float*)d_in[2];
    const float* Wk  = (const float*)d_in[3];
    const float* Wv  = (const float*)d_in[4];
    const float* Wo  = (const float*)d_in[5];
    const float* bo  = (const float*)d_in[6];
    float* out = (float*)d_out;

    cudaFuncSetAttribute(attn_f16,
                         cudaFuncAttributeMaxDynamicSharedMemorySize, ATT_SMEM);

    conv_f2h<<<dim3(160, 5), 256>>>(x, Wq, Wk, Wv, Wo);
    qkv_gemm<<<dim3(DMODEL / BN, MROWS / BM, 3), 256>>>();
    attn_f16<<<dim3(NSEQ / 64, NBATCH * NHEAD), 128, ATT_SMEM>>>(msk);
    out_gemm<<<dim3(DMODEL / BN, OROWS / BM), 256>>>(bo, out);
}